// round 1
// baseline (speedup 1.0000x reference)
#include <cuda_runtime.h>

#define NT  128     // B*T
#define BB  16
#define TT  8
#define CC  512
#define C8  64
#define HW  784
#define HW4 196     // HW / 4

// Scratch (no device allocation allowed -> __device__ globals)
__device__ float g_xv[NT * CC];
__device__ float g_left[NT * C8];
__device__ float g_right[NT * C8];
__device__ float g_sig[NT * CC];

// ---------------------------------------------------------------------------
// Kernel 1: spatial mean pool. One warp per (nt, c) row of 784 floats.
// Grid: 8192 blocks x 256 threads = 65536 warps.
// ---------------------------------------------------------------------------
__global__ void pool_k(const float* __restrict__ x) {
    int w    = (blockIdx.x * blockDim.x + threadIdx.x) >> 5;   // row id 0..65535
    int lane = threadIdx.x & 31;
    const float4* row = reinterpret_cast<const float4*>(x) + (size_t)w * HW4;
    float s = 0.f;
    #pragma unroll 7
    for (int i = lane; i < HW4; i += 32) {
        float4 v = __ldg(row + i);
        s += (v.x + v.y) + (v.z + v.w);
    }
    #pragma unroll
    for (int o = 16; o; o >>= 1) s += __shfl_xor_sync(0xffffffffu, s, o);
    if (lane == 0) g_xv[w] = s * (1.0f / 784.0f);
}

// ---------------------------------------------------------------------------
// Kernel 2: left = relu(BN(xv @ w1^T)), right = relu(BN(xv @ w2^T)).
// One block per nt (128 blocks), 128 threads: tid<64 -> left ch, else right ch.
// ---------------------------------------------------------------------------
__global__ void gemm_bn_k(const float* __restrict__ w1,
                          const float* __restrict__ bn1g, const float* __restrict__ bn1b,
                          const float* __restrict__ bn1m, const float* __restrict__ bn1v,
                          const float* __restrict__ w2,
                          const float* __restrict__ bn2g, const float* __restrict__ bn2b,
                          const float* __restrict__ bn2m, const float* __restrict__ bn2v) {
    __shared__ float sx[CC];
    int nt  = blockIdx.x;
    int tid = threadIdx.x;
    #pragma unroll
    for (int i = tid; i < CC; i += 128) sx[i] = g_xv[nt * CC + i];
    __syncthreads();

    int ch = tid & 63;
    const float* wsel = (tid < 64) ? w1   : w2;
    const float* gsel = (tid < 64) ? bn1g : bn2g;
    const float* bsel = (tid < 64) ? bn1b : bn2b;
    const float* msel = (tid < 64) ? bn1m : bn2m;
    const float* vsel = (tid < 64) ? bn1v : bn2v;

    const float* wr = wsel + ch * CC;
    float a0 = 0.f, a1 = 0.f, a2 = 0.f, a3 = 0.f;
    #pragma unroll 4
    for (int k = 0; k < CC; k += 4) {
        a0 += sx[k + 0] * __ldg(wr + k + 0);
        a1 += sx[k + 1] * __ldg(wr + k + 1);
        a2 += sx[k + 2] * __ldg(wr + k + 2);
        a3 += sx[k + 3] * __ldg(wr + k + 3);
    }
    float acc   = (a0 + a1) + (a2 + a3);
    float scale = gsel[ch] * rsqrtf(vsel[ch] + 1e-5f);
    float val   = fmaxf((acc - msel[ch]) * scale + bsel[ch], 0.f);
    if (tid < 64) g_left[nt * C8 + ch]  = val;
    else          g_right[nt * C8 + ch] = val;
}

// ---------------------------------------------------------------------------
// Kernel 3: gated temporal scan + attention. 16 blocks, each owns a 32-column
// slice of Wa and redundantly replicates the (cheap) state scan.
// ---------------------------------------------------------------------------
__global__ void scan_k(const float* __restrict__ Wa_w, const float* __restrict__ Wa_b,
                       const float* __restrict__ gamma_w, const float* __restrict__ gamma_b) {
    __shared__ float s_gamma[2 * C8];
    __shared__ float s_Wa[32][C8 + 1];   // +1 pad: kill stride-64 bank conflicts
    __shared__ float s_Wab[32];
    __shared__ float s_state[BB][C8];
    __shared__ float s_d[BB][C8];
    __shared__ float s_gate[BB];

    int tid = threadIdx.x;               // 256 threads
    int cs  = blockIdx.x * 32;           // column slice base

    if (tid < 2 * C8) s_gamma[tid] = gamma_w[tid];
    for (int i = tid; i < 32 * C8; i += 256)
        s_Wa[i >> 6][i & 63] = Wa_w[(cs + (i >> 6)) * C8 + (i & 63)];
    if (tid < 32) s_Wab[tid] = Wa_b[cs + tid];
    for (int i = tid; i < BB * C8; i += 256) (&s_state[0][0])[i] = 1.0f;
    float gb = gamma_b[0];
    __syncthreads();

    int warp = tid >> 5, lane = tid & 31;

    for (int t = 0; t < TT; t++) {
        // temporal diff (pad last step with ones)
        for (int i = tid; i < BB * C8; i += 256) {
            int b = i >> 6, k = i & 63;
            int nt = b * TT + t;
            (&s_d[0][0])[i] = (t < TT - 1)
                ? (g_left[nt * C8 + k] - g_right[(nt + 1) * C8 + k]) : 1.0f;
        }
        __syncthreads();

        // gate per batch: dot([d, state], gamma) of length 128, warp-reduced
        for (int bb = warp; bb < BB; bb += 8) {
            float acc = 0.f;
            #pragma unroll
            for (int j = 0; j < 4; j++) {
                int idx = lane + 32 * j;
                float cv = (idx < C8) ? s_d[bb][idx] : s_state[bb][idx - C8];
                acc += cv * s_gamma[idx];
            }
            #pragma unroll
            for (int o = 16; o; o >>= 1) acc += __shfl_xor_sync(0xffffffffu, acc, o);
            if (lane == 0) s_gate[bb] = 1.0f / (1.0f + expf(-(acc + gb)));
        }
        __syncthreads();

        // state update
        for (int i = tid; i < BB * C8; i += 256) {
            int b = i >> 6;
            float g = s_gate[b];
            (&s_state[0][0])[i] = (&s_d[0][0])[i] * g + (&s_state[0][0])[i] * (1.0f - g);
        }
        __syncthreads();

        // attention slice: sigmoid(state @ Wa_slice^T + b)
        for (int p = tid; p < BB * 32; p += 256) {
            int b = p >> 5, c = p & 31;
            float a = s_Wab[c];
            #pragma unroll
            for (int k = 0; k < C8; k++) a += s_state[b][k] * s_Wa[c][k];
            g_sig[(b * TT + t) * CC + cs + c] = 1.0f / (1.0f + expf(-a));
        }
        __syncthreads();
    }
}

// ---------------------------------------------------------------------------
// Kernel 4: out = x * sig (broadcast over H*W). 4 rows per 256-thread block,
// 64 threads per row, float4 I/O. Grid: 16384 blocks.
// ---------------------------------------------------------------------------
__global__ void scale_k(const float* __restrict__ x, float* __restrict__ out) {
    int tid = threadIdx.x;
    int row = blockIdx.x * 4 + (tid >> 6);   // (nt*C + c) row id
    int i   = tid & 63;
    float s = g_sig[row];
    const float4* xi = reinterpret_cast<const float4*>(x)   + (size_t)row * HW4;
    float4*       xo = reinterpret_cast<float4*>(out)       + (size_t)row * HW4;

    float4 v0 = __ldg(xi + i);
    float4 v1 = __ldg(xi + i + 64);
    float4 v2 = __ldg(xi + i + 128);
    v0.x *= s; v0.y *= s; v0.z *= s; v0.w *= s;
    v1.x *= s; v1.y *= s; v1.z *= s; v1.w *= s;
    v2.x *= s; v2.y *= s; v2.z *= s; v2.w *= s;
    xo[i]       = v0;
    xo[i + 64]  = v1;
    xo[i + 128] = v2;
    if (i < HW4 - 192) {                      // tail: 4 float4
        float4 v3 = __ldg(xi + i + 192);
        v3.x *= s; v3.y *= s; v3.z *= s; v3.w *= s;
        xo[i + 192] = v3;
    }
}

// ---------------------------------------------------------------------------
extern "C" void kernel_launch(void* const* d_in, const int* in_sizes, int n_in,
                              void* d_out, int out_size) {
    const float* x       = (const float*)d_in[0];
    const float* w1      = (const float*)d_in[1];
    const float* bn1_g   = (const float*)d_in[2];
    const float* bn1_b   = (const float*)d_in[3];
    const float* bn1_m   = (const float*)d_in[4];
    const float* bn1_v   = (const float*)d_in[5];
    const float* w2      = (const float*)d_in[6];
    const float* bn2_g   = (const float*)d_in[7];
    const float* bn2_b   = (const float*)d_in[8];
    const float* bn2_m   = (const float*)d_in[9];
    const float* bn2_v   = (const float*)d_in[10];
    const float* Wa_w    = (const float*)d_in[11];
    const float* Wa_b    = (const float*)d_in[12];
    const float* gamma_w = (const float*)d_in[13];
    const float* gamma_b = (const float*)d_in[14];
    float* out = (float*)d_out;

    pool_k<<<(NT * CC) / 8, 256>>>(x);                       // 8192 blocks
    gemm_bn_k<<<NT, 128>>>(w1, bn1_g, bn1_b, bn1_m, bn1_v,
                           w2, bn2_g, bn2_b, bn2_m, bn2_v);
    scan_k<<<CC / 32, 256>>>(Wa_w, Wa_b, gamma_w, gamma_b);  // 16 blocks
    scale_k<<<(NT * CC) / 4, 256>>>(x, out);                 // 16384 blocks
}

// round 2
// speedup vs baseline: 1.2267x; 1.2267x over previous
#include <cuda_runtime.h>

#define NT  128     // B*T
#define BB  16
#define TT  8
#define CC  512
#define C8  64
#define HW  784
#define HW4 196     // HW / 4

// Scratch (no device allocation allowed -> __device__ globals)
__device__ float g_xv[NT * CC];
__device__ float g_left[NT * C8];
__device__ float g_right[NT * C8];
__device__ float g_sig[NT * CC];

// ---------------------------------------------------------------------------
// Kernel 1: spatial mean pool. One warp per (nt, c) row of 784 floats.
// Fully unrolled: 6 float4 per lane + predicated tail -> MLP_p1 = 7.
// Reads ASCENDING so L2 ends up holding the TOP of x (scale reads descending).
// ---------------------------------------------------------------------------
__global__ void pool_k(const float* __restrict__ x) {
    int w    = (blockIdx.x * blockDim.x + threadIdx.x) >> 5;   // row id 0..65535
    int lane = threadIdx.x & 31;
    const float4* row = reinterpret_cast<const float4*>(x) + (size_t)w * HW4;

    float4 v0 = row[lane];
    float4 v1 = row[lane + 32];
    float4 v2 = row[lane + 64];
    float4 v3 = row[lane + 96];
    float4 v4 = row[lane + 128];
    float4 v5 = row[lane + 160];
    float s = 0.f;
    if (lane < 4) {                       // tail elems 192..195
        float4 tv = row[192 + lane];
        s = (tv.x + tv.y) + (tv.z + tv.w);
    }
    s += (v0.x + v0.y) + (v0.z + v0.w);
    s += (v1.x + v1.y) + (v1.z + v1.w);
    s += (v2.x + v2.y) + (v2.z + v2.w);
    s += (v3.x + v3.y) + (v3.z + v3.w);
    s += (v4.x + v4.y) + (v4.z + v4.w);
    s += (v5.x + v5.y) + (v5.z + v5.w);

    #pragma unroll
    for (int o = 16; o; o >>= 1) s += __shfl_xor_sync(0xffffffffu, s, o);
    if (lane == 0) g_xv[w] = s * (1.0f / 784.0f);
}

// ---------------------------------------------------------------------------
// Kernel 2: left = relu(BN(xv @ w1^T)), right = relu(BN(xv @ w2^T)).
// One block per nt (128 blocks), 128 threads. float4 weight loads.
// ---------------------------------------------------------------------------
__global__ void gemm_bn_k(const float* __restrict__ w1,
                          const float* __restrict__ bn1g, const float* __restrict__ bn1b,
                          const float* __restrict__ bn1m, const float* __restrict__ bn1v,
                          const float* __restrict__ w2,
                          const float* __restrict__ bn2g, const float* __restrict__ bn2b,
                          const float* __restrict__ bn2m, const float* __restrict__ bn2v) {
    __shared__ float sx[CC];
    int nt  = blockIdx.x;
    int tid = threadIdx.x;
    #pragma unroll
    for (int i = tid; i < CC; i += 128) sx[i] = g_xv[nt * CC + i];
    __syncthreads();

    int ch = tid & 63;
    const float* wsel = (tid < 64) ? w1   : w2;
    const float* gsel = (tid < 64) ? bn1g : bn2g;
    const float* bsel = (tid < 64) ? bn1b : bn2b;
    const float* msel = (tid < 64) ? bn1m : bn2m;
    const float* vsel = (tid < 64) ? bn1v : bn2v;

    const float4* wr4 = reinterpret_cast<const float4*>(wsel + ch * CC);
    const float4* sx4 = reinterpret_cast<const float4*>(sx);
    float a0 = 0.f, a1 = 0.f, a2 = 0.f, a3 = 0.f;
    #pragma unroll 8
    for (int k = 0; k < CC / 4; k++) {
        float4 wv = __ldg(wr4 + k);
        float4 xv = sx4[k];
        a0 += xv.x * wv.x;
        a1 += xv.y * wv.y;
        a2 += xv.z * wv.z;
        a3 += xv.w * wv.w;
    }
    float acc   = (a0 + a1) + (a2 + a3);
    float scale = gsel[ch] * rsqrtf(vsel[ch] + 1e-5f);
    float val   = fmaxf((acc - msel[ch]) * scale + bsel[ch], 0.f);
    if (tid < 64) g_left[nt * C8 + ch]  = val;
    else          g_right[nt * C8 + ch] = val;
}

// ---------------------------------------------------------------------------
// Kernel 3: gated temporal scan + attention. 16 blocks, each owns a 32-column
// slice of Wa and redundantly replicates the (cheap) state scan.
// ---------------------------------------------------------------------------
__global__ void scan_k(const float* __restrict__ Wa_w, const float* __restrict__ Wa_b,
                       const float* __restrict__ gamma_w, const float* __restrict__ gamma_b) {
    __shared__ float s_gamma[2 * C8];
    __shared__ float s_Wa[32][C8 + 1];   // +1 pad: kill stride-64 bank conflicts
    __shared__ float s_Wab[32];
    __shared__ float s_state[BB][C8];
    __shared__ float s_d[BB][C8];
    __shared__ float s_gate[BB];

    int tid = threadIdx.x;               // 256 threads
    int cs  = blockIdx.x * 32;           // column slice base

    if (tid < 2 * C8) s_gamma[tid] = gamma_w[tid];
    for (int i = tid; i < 32 * C8; i += 256)
        s_Wa[i >> 6][i & 63] = Wa_w[(cs + (i >> 6)) * C8 + (i & 63)];
    if (tid < 32) s_Wab[tid] = Wa_b[cs + tid];
    for (int i = tid; i < BB * C8; i += 256) (&s_state[0][0])[i] = 1.0f;
    float gb = gamma_b[0];
    __syncthreads();

    int warp = tid >> 5, lane = tid & 31;

    for (int t = 0; t < TT; t++) {
        // temporal diff (pad last step with ones)
        for (int i = tid; i < BB * C8; i += 256) {
            int b = i >> 6, k = i & 63;
            int nt = b * TT + t;
            (&s_d[0][0])[i] = (t < TT - 1)
                ? (g_left[nt * C8 + k] - g_right[(nt + 1) * C8 + k]) : 1.0f;
        }
        __syncthreads();

        // gate per batch: dot([d, state], gamma) of length 128, warp-reduced
        for (int bb = warp; bb < BB; bb += 8) {
            float acc = 0.f;
            #pragma unroll
            for (int j = 0; j < 4; j++) {
                int idx = lane + 32 * j;
                float cv = (idx < C8) ? s_d[bb][idx] : s_state[bb][idx - C8];
                acc += cv * s_gamma[idx];
            }
            #pragma unroll
            for (int o = 16; o; o >>= 1) acc += __shfl_xor_sync(0xffffffffu, acc, o);
            if (lane == 0) s_gate[bb] = 1.0f / (1.0f + __expf(-(acc + gb)));
        }
        __syncthreads();

        // state update
        for (int i = tid; i < BB * C8; i += 256) {
            int b = i >> 6;
            float g = s_gate[b];
            (&s_state[0][0])[i] = (&s_d[0][0])[i] * g + (&s_state[0][0])[i] * (1.0f - g);
        }
        __syncthreads();

        // attention slice: sigmoid(state @ Wa_slice^T + b)
        for (int p = tid; p < BB * 32; p += 256) {
            int b = p >> 5, c = p & 31;
            float a = s_Wab[c];
            #pragma unroll
            for (int k = 0; k < C8; k++) a += s_state[b][k] * s_Wa[c][k];
            g_sig[(b * TT + t) * CC + cs + c] = 1.0f / (1.0f + __expf(-a));
        }
        __syncthreads();
    }
}

// ---------------------------------------------------------------------------
// Kernel 4: out = x * sig. REVERSE row order: pool left the top ~126MB of x
// resident in L2, so reading descending converts those reads into L2 hits.
// Writes use __stcs (evict-first) so the out stream doesn't evict x lines.
// ---------------------------------------------------------------------------
__global__ void scale_k(const float* __restrict__ x, float* __restrict__ out) {
    int tid = threadIdx.x;
    int rb  = gridDim.x - 1 - blockIdx.x;    // reversed block order
    int row = rb * 4 + (tid >> 6);           // (nt*C + c) row id
    int i   = tid & 63;
    float s = g_sig[row];
    const float4* xi = reinterpret_cast<const float4*>(x)   + (size_t)row * HW4;
    float4*       xo = reinterpret_cast<float4*>(out)       + (size_t)row * HW4;

    float4 v0 = __ldg(xi + i);
    float4 v1 = __ldg(xi + i + 64);
    float4 v2 = __ldg(xi + i + 128);
    float4 v3;
    bool tail = (i < HW4 - 192);
    if (tail) v3 = __ldg(xi + i + 192);
    v0.x *= s; v0.y *= s; v0.z *= s; v0.w *= s;
    v1.x *= s; v1.y *= s; v1.z *= s; v1.w *= s;
    v2.x *= s; v2.y *= s; v2.z *= s; v2.w *= s;
    __stcs(xo + i,       v0);
    __stcs(xo + i + 64,  v1);
    __stcs(xo + i + 128, v2);
    if (tail) {
        v3.x *= s; v3.y *= s; v3.z *= s; v3.w *= s;
        __stcs(xo + i + 192, v3);
    }
}

// ---------------------------------------------------------------------------
extern "C" void kernel_launch(void* const* d_in, const int* in_sizes, int n_in,
                              void* d_out, int out_size) {
    const float* x       = (const float*)d_in[0];
    const float* w1      = (const float*)d_in[1];
    const float* bn1_g   = (const float*)d_in[2];
    const float* bn1_b   = (const float*)d_in[3];
    const float* bn1_m   = (const float*)d_in[4];
    const float* bn1_v   = (const float*)d_in[5];
    const float* w2      = (const float*)d_in[6];
    const float* bn2_g   = (const float*)d_in[7];
    const float* bn2_b   = (const float*)d_in[8];
    const float* bn2_m   = (const float*)d_in[9];
    const float* bn2_v   = (const float*)d_in[10];
    const float* Wa_w    = (const float*)d_in[11];
    const float* Wa_b    = (const float*)d_in[12];
    const float* gamma_w = (const float*)d_in[13];
    const float* gamma_b = (const float*)d_in[14];
    float* out = (float*)d_out;

    pool_k<<<(NT * CC) / 8, 256>>>(x);                       // 8192 blocks
    gemm_bn_k<<<NT, 128>>>(w1, bn1_g, bn1_b, bn1_m, bn1_v,
                           w2, bn2_g, bn2_b, bn2_m, bn2_v);
    scan_k<<<CC / 32, 256>>>(Wa_w, Wa_b, gamma_w, gamma_b);  // 16 blocks
    scale_k<<<(NT * CC) / 4, 256>>>(x, out);                 // 16384 blocks
}

// round 3
// speedup vs baseline: 1.3667x; 1.1142x over previous
#include <cuda_runtime.h>

#define NT  128     // B*T
#define BB  16
#define TT  8
#define CC  512
#define C8  64
#define HW  784
#define HW4 196     // HW / 4

// Scratch (no device allocation allowed -> __device__ globals)
__device__ float g_xv[NT * CC];
__device__ float g_left[NT * C8];
__device__ float g_right[NT * C8];
__device__ float g_state[NT * C8];
__device__ float g_sig[NT * CC];

// ---------------------------------------------------------------------------
// Kernel 1: spatial mean pool. One warp per (nt, c) row of 784 floats.
// Fully unrolled: 6 float4 per lane + predicated tail -> MLP 7.
// ---------------------------------------------------------------------------
__global__ void pool_k(const float* __restrict__ x) {
    int w    = (blockIdx.x * blockDim.x + threadIdx.x) >> 5;   // row id 0..65535
    int lane = threadIdx.x & 31;
    const float4* row = reinterpret_cast<const float4*>(x) + (size_t)w * HW4;

    float4 v0 = row[lane];
    float4 v1 = row[lane + 32];
    float4 v2 = row[lane + 64];
    float4 v3 = row[lane + 96];
    float4 v4 = row[lane + 128];
    float4 v5 = row[lane + 160];
    float s = 0.f;
    if (lane < 4) {                       // tail elems 192..195
        float4 tv = row[192 + lane];
        s = (tv.x + tv.y) + (tv.z + tv.w);
    }
    s += (v0.x + v0.y) + (v0.z + v0.w);
    s += (v1.x + v1.y) + (v1.z + v1.w);
    s += (v2.x + v2.y) + (v2.z + v2.w);
    s += (v3.x + v3.y) + (v3.z + v3.w);
    s += (v4.x + v4.y) + (v4.z + v4.w);
    s += (v5.x + v5.y) + (v5.z + v5.w);

    #pragma unroll
    for (int o = 16; o; o >>= 1) s += __shfl_xor_sync(0xffffffffu, s, o);
    if (lane == 0) g_xv[w] = s * (1.0f / 784.0f);
}

// ---------------------------------------------------------------------------
// Kernel 2: left = relu(BN(xv @ w1^T)), right = relu(BN(xv @ w2^T)).
// ---------------------------------------------------------------------------
__global__ void gemm_bn_k(const float* __restrict__ w1,
                          const float* __restrict__ bn1g, const float* __restrict__ bn1b,
                          const float* __restrict__ bn1m, const float* __restrict__ bn1v,
                          const float* __restrict__ w2,
                          const float* __restrict__ bn2g, const float* __restrict__ bn2b,
                          const float* __restrict__ bn2m, const float* __restrict__ bn2v) {
    __shared__ float sx[CC];
    int nt  = blockIdx.x;
    int tid = threadIdx.x;
    #pragma unroll
    for (int i = tid; i < CC; i += 128) sx[i] = g_xv[nt * CC + i];
    __syncthreads();

    int ch = tid & 63;
    const float* wsel = (tid < 64) ? w1   : w2;
    const float* gsel = (tid < 64) ? bn1g : bn2g;
    const float* bsel = (tid < 64) ? bn1b : bn2b;
    const float* msel = (tid < 64) ? bn1m : bn2m;
    const float* vsel = (tid < 64) ? bn1v : bn2v;

    const float4* wr4 = reinterpret_cast<const float4*>(wsel + ch * CC);
    const float4* sx4 = reinterpret_cast<const float4*>(sx);
    float a0 = 0.f, a1 = 0.f, a2 = 0.f, a3 = 0.f;
    #pragma unroll 8
    for (int k = 0; k < CC / 4; k++) {
        float4 wv = __ldg(wr4 + k);
        float4 xv = sx4[k];
        a0 += xv.x * wv.x;
        a1 += xv.y * wv.y;
        a2 += xv.z * wv.z;
        a3 += xv.w * wv.w;
    }
    float acc   = (a0 + a1) + (a2 + a3);
    float scale = gsel[ch] * rsqrtf(vsel[ch] + 1e-5f);
    float val   = fmaxf((acc - msel[ch]) * scale + bsel[ch], 0.f);
    if (tid < 64) g_left[nt * C8 + ch]  = val;
    else          g_right[nt * C8 + ch] = val;
}

// ---------------------------------------------------------------------------
// Kernel 3a: the TRUE sequential part only. One block, 16 warps (warp = batch).
// All temporal inputs prefetched into registers; recurrence in registers with
// warp shuffles. ~1us total for all 8 steps.
// ---------------------------------------------------------------------------
__global__ void scan_rec_k(const float* __restrict__ gamma_w,
                           const float* __restrict__ gamma_b) {
    int b    = threadIdx.x >> 5;          // 16 warps = 16 batches
    int lane = threadIdx.x & 31;

    float L0[7], L1[7], R0[7], R1[7];
    #pragma unroll
    for (int t = 0; t < 7; t++) {
        L0[t] = g_left [(b * TT + t)     * C8 + lane];
        L1[t] = g_left [(b * TT + t)     * C8 + lane + 32];
        R0[t] = g_right[(b * TT + t + 1) * C8 + lane];
        R1[t] = g_right[(b * TT + t + 1) * C8 + lane + 32];
    }
    float gm0 = __ldg(gamma_w + lane);
    float gm1 = __ldg(gamma_w + lane + 32);
    float gm2 = __ldg(gamma_w + lane + 64);
    float gm3 = __ldg(gamma_w + lane + 96);
    float gb  = __ldg(gamma_b);

    float s0 = 1.f, s1 = 1.f;             // initial state = padded ones
    #pragma unroll
    for (int t = 0; t < TT; t++) {
        float d0 = (t < TT - 1) ? (L0[t] - R0[t]) : 1.f;
        float d1 = (t < TT - 1) ? (L1[t] - R1[t]) : 1.f;
        float acc = d0 * gm0 + d1 * gm1 + s0 * gm2 + s1 * gm3;
        #pragma unroll
        for (int o = 16; o; o >>= 1) acc += __shfl_xor_sync(0xffffffffu, acc, o);
        float g = 1.0f / (1.0f + __expf(-(acc + gb)));
        s0 = d0 * g + s0 * (1.0f - g);
        s1 = d1 * g + s1 * (1.0f - g);
        g_state[(b * TT + t) * C8 + lane]      = s0;
        g_state[(b * TT + t) * C8 + lane + 32] = s1;
    }
}

// ---------------------------------------------------------------------------
// Kernel 3b: attention GEMM (fully parallel): sig = sigmoid(state @ Wa^T + b).
// One block per nt (128 blocks), 256 threads, 2 channels/thread.
// ---------------------------------------------------------------------------
__global__ void att_k(const float* __restrict__ Wa_w, const float* __restrict__ Wa_b) {
    __shared__ float st[C8];
    int nt  = blockIdx.x;
    int tid = threadIdx.x;
    if (tid < C8) st[tid] = g_state[nt * C8 + tid];
    __syncthreads();

    const float4* st4 = reinterpret_cast<const float4*>(st);
    #pragma unroll
    for (int cc = 0; cc < 2; cc++) {
        int c = tid + cc * 256;
        const float4* wr = reinterpret_cast<const float4*>(Wa_w + c * C8);
        float a0 = 0.f, a1 = 0.f, a2 = 0.f, a3 = 0.f;
        #pragma unroll
        for (int k = 0; k < C8 / 4; k++) {
            float4 wv = __ldg(wr + k);
            float4 sv = st4[k];
            a0 += sv.x * wv.x;
            a1 += sv.y * wv.y;
            a2 += sv.z * wv.z;
            a3 += sv.w * wv.w;
        }
        float a = (a0 + a1) + (a2 + a3) + __ldg(Wa_b + c);
        g_sig[nt * CC + c] = 1.0f / (1.0f + __expf(-a));
    }
}

// ---------------------------------------------------------------------------
// Kernel 4: out = x * sig. float4 I/O, streaming stores.
// ---------------------------------------------------------------------------
__global__ void scale_k(const float* __restrict__ x, float* __restrict__ out) {
    int tid = threadIdx.x;
    int rb  = gridDim.x - 1 - blockIdx.x;    // reversed block order
    int row = rb * 4 + (tid >> 6);           // (nt*C + c) row id
    int i   = tid & 63;
    float s = g_sig[row];
    const float4* xi = reinterpret_cast<const float4*>(x)   + (size_t)row * HW4;
    float4*       xo = reinterpret_cast<float4*>(out)       + (size_t)row * HW4;

    float4 v0 = __ldg(xi + i);
    float4 v1 = __ldg(xi + i + 64);
    float4 v2 = __ldg(xi + i + 128);
    float4 v3;
    bool tail = (i < HW4 - 192);
    if (tail) v3 = __ldg(xi + i + 192);
    v0.x *= s; v0.y *= s; v0.z *= s; v0.w *= s;
    v1.x *= s; v1.y *= s; v1.z *= s; v1.w *= s;
    v2.x *= s; v2.y *= s; v2.z *= s; v2.w *= s;
    __stcs(xo + i,       v0);
    __stcs(xo + i + 64,  v1);
    __stcs(xo + i + 128, v2);
    if (tail) {
        v3.x *= s; v3.y *= s; v3.z *= s; v3.w *= s;
        __stcs(xo + i + 192, v3);
    }
}

// ---------------------------------------------------------------------------
extern "C" void kernel_launch(void* const* d_in, const int* in_sizes, int n_in,
                              void* d_out, int out_size) {
    const float* x       = (const float*)d_in[0];
    const float* w1      = (const float*)d_in[1];
    const float* bn1_g   = (const float*)d_in[2];
    const float* bn1_b   = (const float*)d_in[3];
    const float* bn1_m   = (const float*)d_in[4];
    const float* bn1_v   = (const float*)d_in[5];
    const float* w2      = (const float*)d_in[6];
    const float* bn2_g   = (const float*)d_in[7];
    const float* bn2_b   = (const float*)d_in[8];
    const float* bn2_m   = (const float*)d_in[9];
    const float* bn2_v   = (const float*)d_in[10];
    const float* Wa_w    = (const float*)d_in[11];
    const float* Wa_b    = (const float*)d_in[12];
    const float* gamma_w = (const float*)d_in[13];
    const float* gamma_b = (const float*)d_in[14];
    float* out = (float*)d_out;

    pool_k<<<(NT * CC) / 8, 256>>>(x);                       // 8192 blocks
    gemm_bn_k<<<NT, 128>>>(w1, bn1_g, bn1_b, bn1_m, bn1_v,
                           w2, bn2_g, bn2_b, bn2_m, bn2_v);
    scan_rec_k<<<1, 512>>>(gamma_w, gamma_b);                // 1 block, registers
    att_k<<<NT, 256>>>(Wa_w, Wa_b);                          // 128 blocks
    scale_k<<<(NT * CC) / 4, 256>>>(x, out);                 // 16384 blocks
}

// round 4
// speedup vs baseline: 1.3707x; 1.0029x over previous
#include <cuda_runtime.h>

#define NT  128     // B*T
#define BB  16
#define TT  8
#define CC  512
#define C8  64
#define HW  784
#define HW4 196     // HW / 4

// Scratch (no device allocation allowed -> __device__ globals)
__device__ float g_xv[NT * CC];
__device__ float g_left[NT * C8];
__device__ float g_right[NT * C8];
__device__ float g_state[NT * C8];

// ---------------------------------------------------------------------------
// Kernel 1: spatial mean pool. One warp per (nt, c) row of 784 floats.
// Fully unrolled: 6 float4 per lane + predicated tail -> MLP 7.
// ---------------------------------------------------------------------------
__global__ void pool_k(const float* __restrict__ x) {
    int w    = (blockIdx.x * blockDim.x + threadIdx.x) >> 5;   // row id 0..65535
    int lane = threadIdx.x & 31;
    const float4* row = reinterpret_cast<const float4*>(x) + (size_t)w * HW4;

    float4 v0 = row[lane];
    float4 v1 = row[lane + 32];
    float4 v2 = row[lane + 64];
    float4 v3 = row[lane + 96];
    float4 v4 = row[lane + 128];
    float4 v5 = row[lane + 160];
    float s = 0.f;
    if (lane < 4) {                       // tail elems 192..195
        float4 tv = row[192 + lane];
        s = (tv.x + tv.y) + (tv.z + tv.w);
    }
    s += (v0.x + v0.y) + (v0.z + v0.w);
    s += (v1.x + v1.y) + (v1.z + v1.w);
    s += (v2.x + v2.y) + (v2.z + v2.w);
    s += (v3.x + v3.y) + (v3.z + v3.w);
    s += (v4.x + v4.y) + (v4.z + v4.w);
    s += (v5.x + v5.y) + (v5.z + v5.w);

    #pragma unroll
    for (int o = 16; o; o >>= 1) s += __shfl_xor_sync(0xffffffffu, s, o);
    if (lane == 0) g_xv[w] = s * (1.0f / 784.0f);
}

// ---------------------------------------------------------------------------
// Kernel 2: left = relu(BN(xv @ w1^T)), right = relu(BN(xv @ w2^T)).
// ---------------------------------------------------------------------------
__global__ void gemm_bn_k(const float* __restrict__ w1,
                          const float* __restrict__ bn1g, const float* __restrict__ bn1b,
                          const float* __restrict__ bn1m, const float* __restrict__ bn1v,
                          const float* __restrict__ w2,
                          const float* __restrict__ bn2g, const float* __restrict__ bn2b,
                          const float* __restrict__ bn2m, const float* __restrict__ bn2v) {
    __shared__ float sx[CC];
    int nt  = blockIdx.x;
    int tid = threadIdx.x;
    #pragma unroll
    for (int i = tid; i < CC; i += 128) sx[i] = g_xv[nt * CC + i];
    __syncthreads();

    int ch = tid & 63;
    const float* wsel = (tid < 64) ? w1   : w2;
    const float* gsel = (tid < 64) ? bn1g : bn2g;
    const float* bsel = (tid < 64) ? bn1b : bn2b;
    const float* msel = (tid < 64) ? bn1m : bn2m;
    const float* vsel = (tid < 64) ? bn1v : bn2v;

    const float4* wr4 = reinterpret_cast<const float4*>(wsel + ch * CC);
    const float4* sx4 = reinterpret_cast<const float4*>(sx);
    float a0 = 0.f, a1 = 0.f, a2 = 0.f, a3 = 0.f;
    #pragma unroll 8
    for (int k = 0; k < CC / 4; k++) {
        float4 wv = __ldg(wr4 + k);
        float4 xv = sx4[k];
        a0 += xv.x * wv.x;
        a1 += xv.y * wv.y;
        a2 += xv.z * wv.z;
        a3 += xv.w * wv.w;
    }
    float acc   = (a0 + a1) + (a2 + a3);
    float scale = gsel[ch] * rsqrtf(vsel[ch] + 1e-5f);
    float val   = fmaxf((acc - msel[ch]) * scale + bsel[ch], 0.f);
    if (tid < 64) g_left[nt * C8 + ch]  = val;
    else          g_right[nt * C8 + ch] = val;
}

// ---------------------------------------------------------------------------
// Kernel 3: the TRUE sequential part only. One block, 16 warps (warp = batch).
// All temporal inputs prefetched into registers; recurrence in registers with
// warp shuffles.
// ---------------------------------------------------------------------------
__global__ void scan_rec_k(const float* __restrict__ gamma_w,
                           const float* __restrict__ gamma_b) {
    int b    = threadIdx.x >> 5;          // 16 warps = 16 batches
    int lane = threadIdx.x & 31;

    float L0[7], L1[7], R0[7], R1[7];
    #pragma unroll
    for (int t = 0; t < 7; t++) {
        L0[t] = g_left [(b * TT + t)     * C8 + lane];
        L1[t] = g_left [(b * TT + t)     * C8 + lane + 32];
        R0[t] = g_right[(b * TT + t + 1) * C8 + lane];
        R1[t] = g_right[(b * TT + t + 1) * C8 + lane + 32];
    }
    float gm0 = __ldg(gamma_w + lane);
    float gm1 = __ldg(gamma_w + lane + 32);
    float gm2 = __ldg(gamma_w + lane + 64);
    float gm3 = __ldg(gamma_w + lane + 96);
    float gb  = __ldg(gamma_b);

    float s0 = 1.f, s1 = 1.f;             // initial state = padded ones
    #pragma unroll
    for (int t = 0; t < TT; t++) {
        float d0 = (t < TT - 1) ? (L0[t] - R0[t]) : 1.f;
        float d1 = (t < TT - 1) ? (L1[t] - R1[t]) : 1.f;
        float acc = d0 * gm0 + d1 * gm1 + s0 * gm2 + s1 * gm3;
        #pragma unroll
        for (int o = 16; o; o >>= 1) acc += __shfl_xor_sync(0xffffffffu, acc, o);
        float g = 1.0f / (1.0f + __expf(-(acc + gb)));
        s0 = d0 * g + s0 * (1.0f - g);
        s1 = d1 * g + s1 * (1.0f - g);
        g_state[(b * TT + t) * C8 + lane]      = s0;
        g_state[(b * TT + t) * C8 + lane + 32] = s1;
    }
}

// ---------------------------------------------------------------------------
// Kernel 4: FUSED attention + scale.
// Block = 4 consecutive (nt,c) rows (all sharing one nt). Each 64-thread
// row-group computes sig = sigmoid(dot(state[nt], Wa[c]) + Wa_b[c]) inline
// (one element per thread, shuffle + 2-slot smem reduce), then scales its
// 784 x values. x loads are issued before the dot so the DRAM stream hides
// the reduction latency.
// ---------------------------------------------------------------------------
__global__ void scale_att_k(const float* __restrict__ x,
                            const float* __restrict__ Wa_w,
                            const float* __restrict__ Wa_b,
                            float* __restrict__ out) {
    __shared__ float s_part[4][2];
    int tid  = threadIdx.x;
    int sub  = tid >> 6;                     // row-group 0..3
    int i    = tid & 63;                     // lane within group
    int row  = blockIdx.x * 4 + sub;         // (nt*CC + c) row id
    int nt   = row >> 9;                     // /CC

    const float4* xi = reinterpret_cast<const float4*>(x)   + (size_t)row * HW4;
    float4*       xo = reinterpret_cast<float4*>(out)       + (size_t)row * HW4;

    // issue bulk loads first (long-latency, overlap with sig computation)
    float4 v0 = __ldg(xi + i);
    float4 v1 = __ldg(xi + i + 64);
    float4 v2 = __ldg(xi + i + 128);
    float4 v3;
    bool tail = (i < HW4 - 192);
    if (tail) v3 = __ldg(xi + i + 192);

    // inline attention dot: state[nt][i] * Wa[c][i], 64 threads, 1 elem each
    float p = g_state[nt * C8 + i] * __ldg(Wa_w + row * C8 + i);  // row*C8 == c*C8 globally? no:
    // NOTE: Wa_w is [CC][C8]; the row index into Wa is c = row % CC == (row & 511).
    // row*C8 would be wrong -> fix with (row & 511).
    p = g_state[nt * C8 + i] * __ldg(Wa_w + (row & (CC - 1)) * C8 + i);
    #pragma unroll
    for (int o = 16; o; o >>= 1) p += __shfl_xor_sync(0xffffffffu, p, o);
    if ((i & 31) == 0) s_part[sub][i >> 5] = p;
    __syncthreads();
    float a = s_part[sub][0] + s_part[sub][1] + __ldg(Wa_b + (row & (CC - 1)));
    float s = 1.0f / (1.0f + __expf(-a));

    v0.x *= s; v0.y *= s; v0.z *= s; v0.w *= s;
    v1.x *= s; v1.y *= s; v1.z *= s; v1.w *= s;
    v2.x *= s; v2.y *= s; v2.z *= s; v2.w *= s;
    __stcs(xo + i,       v0);
    __stcs(xo + i + 64,  v1);
    __stcs(xo + i + 128, v2);
    if (tail) {
        v3.x *= s; v3.y *= s; v3.z *= s; v3.w *= s;
        __stcs(xo + i + 192, v3);
    }
}

// ---------------------------------------------------------------------------
extern "C" void kernel_launch(void* const* d_in, const int* in_sizes, int n_in,
                              void* d_out, int out_size) {
    const float* x       = (const float*)d_in[0];
    const float* w1      = (const float*)d_in[1];
    const float* bn1_g   = (const float*)d_in[2];
    const float* bn1_b   = (const float*)d_in[3];
    const float* bn1_m   = (const float*)d_in[4];
    const float* bn1_v   = (const float*)d_in[5];
    const float* w2      = (const float*)d_in[6];
    const float* bn2_g   = (const float*)d_in[7];
    const float* bn2_b   = (const float*)d_in[8];
    const float* bn2_m   = (const float*)d_in[9];
    const float* bn2_v   = (const float*)d_in[10];
    const float* Wa_w    = (const float*)d_in[11];
    const float* Wa_b    = (const float*)d_in[12];
    const float* gamma_w = (const float*)d_in[13];
    const float* gamma_b = (const float*)d_in[14];
    float* out = (float*)d_out;

    pool_k<<<(NT * CC) / 8, 256>>>(x);                       // 8192 blocks
    gemm_bn_k<<<NT, 128>>>(w1, bn1_g, bn1_b, bn1_m, bn1_v,
                           w2, bn2_g, bn2_b, bn2_m, bn2_v);
    scan_rec_k<<<1, 512>>>(gamma_w, gamma_b);                // 1 block, registers
    scale_att_k<<<(NT * CC) / 4, 256>>>(x, Wa_w, Wa_b, out); // 16384 blocks
}

// round 5
// speedup vs baseline: 1.3729x; 1.0016x over previous
#include <cuda_runtime.h>

#define NT  128     // B*T
#define BB  16
#define TT  8
#define CC  512
#define C8  64
#define HW  784
#define HW4 196     // HW / 4

// Scratch (no device allocation allowed -> __device__ globals)
__device__ float g_xv[NT * CC];
__device__ float g_left[NT * C8];
__device__ float g_right[NT * C8];
__device__ float g_state[NT * C8];

// ---------------------------------------------------------------------------
// Kernel 1: spatial mean pool, restructured to scale_att_k's proven access
// pattern: 4 rows per 256-thread block, 64 threads per row, 3(+1 tail)
// float4 loads per thread (front-batched MLP=4, not 7 -> avoids the
// cross-CTA L1tex-queue spread regime). 64-thread reduce via shuffle + smem.
// ---------------------------------------------------------------------------
__global__ void pool_k(const float* __restrict__ x) {
    __shared__ float s_part[4][2];
    int tid = threadIdx.x;
    int sub = tid >> 6;                      // row-group 0..3
    int i   = tid & 63;                      // lane within group
    int row = blockIdx.x * 4 + sub;          // (nt*CC + c) row id
    const float4* xi = reinterpret_cast<const float4*>(x) + (size_t)row * HW4;

    float4 v0 = xi[i];
    float4 v1 = xi[i + 64];
    float4 v2 = xi[i + 128];
    float s = 0.f;
    if (i < HW4 - 192) {                     // tail: 4 float4
        float4 tv = xi[i + 192];
        s = (tv.x + tv.y) + (tv.z + tv.w);
    }
    s += (v0.x + v0.y) + (v0.z + v0.w);
    s += (v1.x + v1.y) + (v1.z + v1.w);
    s += (v2.x + v2.y) + (v2.z + v2.w);

    #pragma unroll
    for (int o = 16; o; o >>= 1) s += __shfl_xor_sync(0xffffffffu, s, o);
    if ((i & 31) == 0) s_part[sub][i >> 5] = s;
    __syncthreads();
    if (i == 0)
        g_xv[row] = (s_part[sub][0] + s_part[sub][1]) * (1.0f / 784.0f);
}

// ---------------------------------------------------------------------------
// Kernel 2: left = relu(BN(xv @ w1^T)), right = relu(BN(xv @ w2^T)).
// ---------------------------------------------------------------------------
__global__ void gemm_bn_k(const float* __restrict__ w1,
                          const float* __restrict__ bn1g, const float* __restrict__ bn1b,
                          const float* __restrict__ bn1m, const float* __restrict__ bn1v,
                          const float* __restrict__ w2,
                          const float* __restrict__ bn2g, const float* __restrict__ bn2b,
                          const float* __restrict__ bn2m, const float* __restrict__ bn2v) {
    __shared__ float sx[CC];
    int nt  = blockIdx.x;
    int tid = threadIdx.x;
    #pragma unroll
    for (int i = tid; i < CC; i += 128) sx[i] = g_xv[nt * CC + i];
    __syncthreads();

    int ch = tid & 63;
    const float* wsel = (tid < 64) ? w1   : w2;
    const float* gsel = (tid < 64) ? bn1g : bn2g;
    const float* bsel = (tid < 64) ? bn1b : bn2b;
    const float* msel = (tid < 64) ? bn1m : bn2m;
    const float* vsel = (tid < 64) ? bn1v : bn2v;

    const float4* wr4 = reinterpret_cast<const float4*>(wsel + ch * CC);
    const float4* sx4 = reinterpret_cast<const float4*>(sx);
    float a0 = 0.f, a1 = 0.f, a2 = 0.f, a3 = 0.f;
    #pragma unroll 8
    for (int k = 0; k < CC / 4; k++) {
        float4 wv = __ldg(wr4 + k);
        float4 xv = sx4[k];
        a0 += xv.x * wv.x;
        a1 += xv.y * wv.y;
        a2 += xv.z * wv.z;
        a3 += xv.w * wv.w;
    }
    float acc   = (a0 + a1) + (a2 + a3);
    float scale = gsel[ch] * rsqrtf(vsel[ch] + 1e-5f);
    float val   = fmaxf((acc - msel[ch]) * scale + bsel[ch], 0.f);
    if (tid < 64) g_left[nt * C8 + ch]  = val;
    else          g_right[nt * C8 + ch] = val;
}

// ---------------------------------------------------------------------------
// Kernel 3: the TRUE sequential part only. One block, 16 warps (warp = batch).
// All temporal inputs prefetched into registers; recurrence in registers with
// warp shuffles.
// ---------------------------------------------------------------------------
__global__ void scan_rec_k(const float* __restrict__ gamma_w,
                           const float* __restrict__ gamma_b) {
    int b    = threadIdx.x >> 5;          // 16 warps = 16 batches
    int lane = threadIdx.x & 31;

    float L0[7], L1[7], R0[7], R1[7];
    #pragma unroll
    for (int t = 0; t < 7; t++) {
        L0[t] = g_left [(b * TT + t)     * C8 + lane];
        L1[t] = g_left [(b * TT + t)     * C8 + lane + 32];
        R0[t] = g_right[(b * TT + t + 1) * C8 + lane];
        R1[t] = g_right[(b * TT + t + 1) * C8 + lane + 32];
    }
    float gm0 = __ldg(gamma_w + lane);
    float gm1 = __ldg(gamma_w + lane + 32);
    float gm2 = __ldg(gamma_w + lane + 64);
    float gm3 = __ldg(gamma_w + lane + 96);
    float gb  = __ldg(gamma_b);

    float s0 = 1.f, s1 = 1.f;             // initial state = padded ones
    #pragma unroll
    for (int t = 0; t < TT; t++) {
        float d0 = (t < TT - 1) ? (L0[t] - R0[t]) : 1.f;
        float d1 = (t < TT - 1) ? (L1[t] - R1[t]) : 1.f;
        float acc = d0 * gm0 + d1 * gm1 + s0 * gm2 + s1 * gm3;
        #pragma unroll
        for (int o = 16; o; o >>= 1) acc += __shfl_xor_sync(0xffffffffu, acc, o);
        float g = 1.0f / (1.0f + __expf(-(acc + gb)));
        s0 = d0 * g + s0 * (1.0f - g);
        s1 = d1 * g + s1 * (1.0f - g);
        g_state[(b * TT + t) * C8 + lane]      = s0;
        g_state[(b * TT + t) * C8 + lane + 32] = s1;
    }
}

// ---------------------------------------------------------------------------
// Kernel 4: FUSED attention + scale. Block = 4 rows sharing one nt; each
// 64-thread group computes its sigmoid dot inline, then scales 784 x values.
// ---------------------------------------------------------------------------
__global__ void scale_att_k(const float* __restrict__ x,
                            const float* __restrict__ Wa_w,
                            const float* __restrict__ Wa_b,
                            float* __restrict__ out) {
    __shared__ float s_part[4][2];
    int tid  = threadIdx.x;
    int sub  = tid >> 6;                     // row-group 0..3
    int i    = tid & 63;                     // lane within group
    int row  = blockIdx.x * 4 + sub;         // (nt*CC + c) row id
    int nt   = row >> 9;                     // /CC
    int c    = row & (CC - 1);

    const float4* xi = reinterpret_cast<const float4*>(x)   + (size_t)row * HW4;
    float4*       xo = reinterpret_cast<float4*>(out)       + (size_t)row * HW4;

    // issue bulk loads first (long-latency, overlap with sig computation)
    float4 v0 = __ldg(xi + i);
    float4 v1 = __ldg(xi + i + 64);
    float4 v2 = __ldg(xi + i + 128);
    float4 v3;
    bool tail = (i < HW4 - 192);
    if (tail) v3 = __ldg(xi + i + 192);

    // inline attention dot: state[nt][i] * Wa[c][i], 64 threads, 1 elem each
    float p = g_state[nt * C8 + i] * __ldg(Wa_w + c * C8 + i);
    #pragma unroll
    for (int o = 16; o; o >>= 1) p += __shfl_xor_sync(0xffffffffu, p, o);
    if ((i & 31) == 0) s_part[sub][i >> 5] = p;
    __syncthreads();
    float a = s_part[sub][0] + s_part[sub][1] + __ldg(Wa_b + c);
    float s = 1.0f / (1.0f + __expf(-a));

    v0.x *= s; v0.y *= s; v0.z *= s; v0.w *= s;
    v1.x *= s; v1.y *= s; v1.z *= s; v1.w *= s;
    v2.x *= s; v2.y *= s; v2.z *= s; v2.w *= s;
    __stcs(xo + i,       v0);
    __stcs(xo + i + 64,  v1);
    __stcs(xo + i + 128, v2);
    if (tail) {
        v3.x *= s; v3.y *= s; v3.z *= s; v3.w *= s;
        __stcs(xo + i + 192, v3);
    }
}

// ---------------------------------------------------------------------------
extern "C" void kernel_launch(void* const* d_in, const int* in_sizes, int n_in,
                              void* d_out, int out_size) {
    const float* x       = (const float*)d_in[0];
    const float* w1      = (const float*)d_in[1];
    const float* bn1_g   = (const float*)d_in[2];
    const float* bn1_b   = (const float*)d_in[3];
    const float* bn1_m   = (const float*)d_in[4];
    const float* bn1_v   = (const float*)d_in[5];
    const float* w2      = (const float*)d_in[6];
    const float* bn2_g   = (const float*)d_in[7];
    const float* bn2_b   = (const float*)d_in[8];
    const float* bn2_m   = (const float*)d_in[9];
    const float* bn2_v   = (const float*)d_in[10];
    const float* Wa_w    = (const float*)d_in[11];
    const float* Wa_b    = (const float*)d_in[12];
    const float* gamma_w = (const float*)d_in[13];
    const float* gamma_b = (const float*)d_in[14];
    float* out = (float*)d_out;

    pool_k<<<(NT * CC) / 4, 256>>>(x);                       // 16384 blocks
    gemm_bn_k<<<NT, 128>>>(w1, bn1_g, bn1_b, bn1_m, bn1_v,
                           w2, bn2_g, bn2_b, bn2_m, bn2_v);
    scan_rec_k<<<1, 512>>>(gamma_w, gamma_b);                // 1 block, registers
    scale_att_k<<<(NT * CC) / 4, 256>>>(x, Wa_w, Wa_b, out); // 16384 blocks
}